// round 17
// baseline (speedup 1.0000x reference)
#include <cuda_runtime.h>
#include <cuda_bf16.h>
#include <math.h>
#include <stdint.h>

#define N_NODES 50000
#define N_EDGES 600000
#define DD 128
#define BN_EPS 1e-5f
#define NT64 782     // ceil(50000/64)

// ---------------- scratch (device globals; no allocation allowed) ----------------
__device__ float g_agg [(size_t)N_NODES * DD];
__device__ float g_h2  [(size_t)N_NODES * DD];
__device__ float g_statsL[7][2 * DD];            // per-layer column sum / sumsq
// CSR scratch
__device__ int g_cnt [N_NODES];
__device__ int g_fill[N_NODES];
__device__ int g_off [N_NODES + 1];
__device__ int g_bsum[256];
__device__ int g_csr_src[N_EDGES];
// pre-packed bf16 weight fragment images: [14 mats][hi/lo][128*128] u16
__device__ unsigned short g_wimg[14][2][DD * DD];
// cached A fragments (hi/lo) for layers 3-6 stage-1: per 64-row tile, 32 frags x 512B
__device__ unsigned char g_aimg[2][(size_t)NT64 * 32 * 512];

static __device__ __forceinline__ unsigned short bfbits(float f) {
    __nv_bfloat16 h = __float2bfloat16(f);
    return *reinterpret_cast<unsigned short*>(&h);
}
static __device__ __forceinline__ float bf2f(unsigned short u) {
    __nv_bfloat16 h = *reinterpret_cast<__nv_bfloat16*>(&u);
    return __bfloat162float(h);
}
static __device__ __forceinline__ uint32_t pack_bf2(float f0, float f1) {
    return (uint32_t)bfbits(f0) | ((uint32_t)bfbits(f1) << 16);
}

// ================= CSR build =================
__global__ void zero_cnt_kernel() {
    int i = blockIdx.x * 256 + threadIdx.x;
    if (i < N_NODES) { g_cnt[i] = 0; g_fill[i] = 0; }
    if (i < 7 * 2 * DD) ((float*)g_statsL)[i] = 0.f;
}
__global__ void hist_kernel(const int* __restrict__ dst) {
    int e = blockIdx.x * 256 + threadIdx.x;
    if (e < N_EDGES) {
        int d = dst[e];
        if ((unsigned)d < N_NODES) atomicAdd(&g_cnt[d], 1);
    }
}
__global__ void __launch_bounds__(256) scan1_kernel() {
    int t = threadIdx.x, b = blockIdx.x;
    int i = b * 256 + t;
    int v = (i < N_NODES) ? g_cnt[i] : 0;
    __shared__ int sm[256];
    sm[t] = v;
    __syncthreads();
#pragma unroll
    for (int d = 1; d < 256; d <<= 1) {
        int u = (t >= d) ? sm[t - d] : 0;
        __syncthreads();
        sm[t] += u;
        __syncthreads();
    }
    if (i <= N_NODES) g_off[i] = sm[t] - v;
    if (t == 255) g_bsum[b] = sm[255];
}
__global__ void __launch_bounds__(256) scan2_kernel(int nblocks) {
    int t = threadIdx.x;
    int v = (t < nblocks) ? g_bsum[t] : 0;
    __shared__ int sm[256];
    sm[t] = v;
    __syncthreads();
#pragma unroll
    for (int d = 1; d < 256; d <<= 1) {
        int u = (t >= d) ? sm[t - d] : 0;
        __syncthreads();
        sm[t] += u;
        __syncthreads();
    }
    if (t < nblocks) g_bsum[t] = sm[t] - v;
}
__global__ void __launch_bounds__(256) scan3_kernel() {
    int t = threadIdx.x, b = blockIdx.x;
    int i = b * 256 + t;
    if (i < N_NODES) {
        int o = g_off[i] + g_bsum[b];
        g_off[i] = o;
        if (i == N_NODES - 1) g_off[N_NODES] = o + g_cnt[i];
    }
}
__global__ void fill_kernel(const int* __restrict__ src, const int* __restrict__ dst) {
    int e = blockIdx.x * 256 + threadIdx.x;
    if (e < N_EDGES) {
        int d = dst[e];
        int s = src[e];
        if ((unsigned)d < N_NODES && (unsigned)s < N_NODES) {
            int p = g_off[d] + atomicAdd(&g_fill[d], 1);
            g_csr_src[p] = s;
        }
    }
}

// ================= weight convert: fp32 W[k][n] -> B-fragment images (hi/lo) =================
__global__ void wconv_kernel(const float* __restrict__ W1, const float* __restrict__ W2) {
    int t = blockIdx.x * 256 + threadIdx.x;
    if (t >= 14 * DD * DD) return;
    int mat = t >> 14;
    int e   = t & 16383;
    int k = e >> 7, n = e & 127;
    const float* Wsrc = (mat & 1) ? W2 : W1;
    float v = Wsrc[(size_t)(mat >> 1) * DD * DD + e];
    unsigned short hb = bfbits(v);
    unsigned short lb = bfbits(v - bf2f(hb));
    int ks = k >> 4, kk = k & 15;
    int ns = n >> 3, nn = n & 7;
    int lane = nn * 4 + ((kk & 7) >> 1);
    int reg  = kk >> 3;
    int elem = kk & 1;
    int idx = ((((ks * 16 + ns) * 32 + lane) * 2 + reg) * 2 + elem);
    g_wimg[mat][0][idx] = hb;
    g_wimg[mat][1][idx] = lb;
}

// ================= aggregation (CSR gather, raw sum) =================
__global__ void __launch_bounds__(256) agg_kernel(const float* __restrict__ x) {
    int t = blockIdx.x * 256 + threadIdx.x;
    int node = t >> 5;
    if (node >= N_NODES) return;
    int lane = t & 31;
    int beg = g_off[node], end = g_off[node + 1];
    float4 acc = make_float4(0.f, 0.f, 0.f, 0.f);
    for (int i = beg; i < end; i++) {
        int s = g_csr_src[i];
        float4 v = *(const float4*)(x + (size_t)s * DD + lane * 4);
        acc.x += v.x; acc.y += v.y; acc.z += v.z; acc.w += v.w;
    }
    *(float4*)(g_agg + (size_t)node * DD + lane * 4) = acc;
}

// ================= fused layer kernel (BM=64): out = act2(relu(A@W1+b1)@W2+b2) =================
// FMODE 0: A = affine(xin+agg,deg); act2=relu -> g_h2 (+stats)    (GC layers 0-2)
// FMODE 1: like 0 but dump A-frags to g_aimg; act2=tanh -> outP   (layer 3)
// FMODE 2: A from g_aimg; act2=tanh -> outP                       (layers 4-6)
#define FRAG_STRIDE 528
#define NFRAG 32                          // 4 msub x 8 ks
#define A_MAT_BYTES (NFRAG * FRAG_STRIDE) // 16896
#define STAT_BYTES  1024
#define SMEM_BYTES  (2 * A_MAT_BYTES + STAT_BYTES)   // 34816

#define MMA_BF16(d, a, b) \
    asm volatile("mma.sync.aligned.m16n8k16.row.col.f32.bf16.bf16.f32 " \
                 "{%0,%1,%2,%3},{%4,%5,%6,%7},{%8,%9},{%0,%1,%2,%3};" \
                 : "+f"(d[0]), "+f"(d[1]), "+f"(d[2]), "+f"(d[3]) \
                 : "r"(a.x), "r"(a.y), "r"(a.z), "r"(a.w), "r"(b.x), "r"(b.y))

template <int FMODE>
__global__ void __launch_bounds__(256) fused_mma(
    const float* __restrict__ xin, int mat,
    const float* __restrict__ bias1, const float* __restrict__ bias2,
    float* __restrict__ statsOut,
    const float* __restrict__ bnstats,
    const float* __restrict__ gammaL, const float* __restrict__ betaL,
    float* __restrict__ outP)
{
    extern __shared__ char smem[];
    float* sstat = (float*)(smem + 2 * A_MAT_BYTES);
    const int tid  = threadIdx.x;
    const int wid  = tid >> 5;
    const int lane = tid & 31;
    const int mbase = blockIdx.x * 64;
    const int warp_m = wid >> 1;   // 0..3  (16-row slice)
    const int warp_n = wid & 1;    // 0..1  (64-col slice)

    sstat[tid] = 0.f;

    if (FMODE != 2) {
        // ---- stage A: fp32 (+agg, BN affine of prev layer), split hi/lo, frag order ----
        const int rr  = tid >> 4;          // 0..15
        const int col = (tid & 15) * 8;
        const int ks  = col >> 4;
        const int p   = ((rr & 15) >= 8 ? 1 : 0) + (((col & 15) >= 8) ? 2 : 0);
        float sv[8], tv[8];
        if (bnstats) {
#pragma unroll
            for (int j = 0; j < 8; j++) {
                int c = col + j;
                float mean = __ldg(&bnstats[c]) * (1.0f / N_NODES);
                float var  = __ldg(&bnstats[DD + c]) * (1.0f / N_NODES) - mean * mean;
                float rstd = rsqrtf(var + BN_EPS);
                sv[j] = __ldg(&gammaL[c]) * rstd;
                tv[j] = __ldg(&betaL[c]) - mean * sv[j];
            }
        } else {
#pragma unroll
            for (int j = 0; j < 8; j++) { sv[j] = 1.f; tv[j] = 0.f; }
        }
#pragma unroll
        for (int msub = 0; msub < 4; msub++) {
            int m = mbase + msub * 16 + rr;
            float v[8];
            if (m < N_NODES) {
                size_t off = (size_t)m * DD + col;
                float4 p0 = *(const float4*)(xin + off);
                float4 p1 = *(const float4*)(xin + off + 4);
                float4 a0 = *(const float4*)(g_agg + off);
                float4 a1 = *(const float4*)(g_agg + off + 4);
                p0.x += a0.x; p0.y += a0.y; p0.z += a0.z; p0.w += a0.w;
                p1.x += a1.x; p1.y += a1.y; p1.z += a1.z; p1.w += a1.w;
                float cnt = 1.0f + (float)(g_off[m + 1] - g_off[m]);
                v[0] = sv[0] * p0.x + cnt * tv[0];
                v[1] = sv[1] * p0.y + cnt * tv[1];
                v[2] = sv[2] * p0.z + cnt * tv[2];
                v[3] = sv[3] * p0.w + cnt * tv[3];
                v[4] = sv[4] * p1.x + cnt * tv[4];
                v[5] = sv[5] * p1.y + cnt * tv[5];
                v[6] = sv[6] * p1.z + cnt * tv[6];
                v[7] = sv[7] * p1.w + cnt * tv[7];
            } else {
#pragma unroll
                for (int j = 0; j < 8; j++) v[j] = 0.f;
            }
            int frag = msub * 8 + ks;
            int fbase = frag * FRAG_STRIDE + p * 4;
            size_t gbase = ((size_t)blockIdx.x * NFRAG + frag) * 512 + p * 4;
#pragma unroll
            for (int j = 0; j < 4; j++) {
                float f0 = v[2 * j], f1 = v[2 * j + 1];
                uint32_t hb0 = bfbits(f0), hb1 = bfbits(f1);
                uint32_t hp = hb0 | (hb1 << 16);
                uint32_t lp = pack_bf2(f0 - bf2f((unsigned short)hb0),
                                       f1 - bf2f((unsigned short)hb1));
                int lane_w = (rr & 7) * 4 + j;
                *(uint32_t*)(smem + fbase + lane_w * 16)               = hp;
                *(uint32_t*)(smem + A_MAT_BYTES + fbase + lane_w * 16) = lp;
                if (FMODE == 1) {
                    *(uint32_t*)(&g_aimg[0][gbase + lane_w * 16]) = hp;
                    *(uint32_t*)(&g_aimg[1][gbase + lane_w * 16]) = lp;
                }
            }
        }
    }
    __syncthreads();

    float acc[8][4];

    // =========== MMA stage 1: A @ W1  (warp tile 16x64) ===========
#pragma unroll
    for (int j = 0; j < 8; j++)
#pragma unroll
        for (int q = 0; q < 4; q++) acc[j][q] = 0.f;
    {
        const uint2* wh = (const uint2*)&g_wimg[mat][0][0];
        const uint2* wl = (const uint2*)&g_wimg[mat][1][0];
#pragma unroll
        for (int k8 = 0; k8 < 8; k8++) {
            uint4 ah, al;
            int frag = warp_m * 8 + k8;
            if (FMODE == 2) {
                size_t gb = ((size_t)blockIdx.x * NFRAG + frag) * 512 + lane * 16;
                ah = __ldg((const uint4*)&g_aimg[0][gb]);
                al = __ldg((const uint4*)&g_aimg[1][gb]);
            } else {
                int fb = frag * FRAG_STRIDE + lane * 16;
                ah = *(const uint4*)(smem + fb);
                al = *(const uint4*)(smem + A_MAT_BYTES + fb);
            }
            uint2 bh[8], bl[8];
#pragma unroll
            for (int ns = 0; ns < 8; ns++) {
                int bi = (k8 * 16 + warp_n * 8 + ns) * 32 + lane;
                bh[ns] = __ldg(&wh[bi]);
                bl[ns] = __ldg(&wl[bi]);
            }
#pragma unroll
            for (int ns = 0; ns < 8; ns++) {
                MMA_BF16(acc[ns], ah, bh[ns]);
                MMA_BF16(acc[ns], ah, bl[ns]);
                MMA_BF16(acc[ns], al, bh[ns]);
            }
        }
    }

    // =========== convert h1 = relu(acc + b1) -> smem fragments (in place) ===========
    __syncthreads();   // all A reads done before overwrite
#pragma unroll
    for (int ns = 0; ns < 8; ns++) {
        int c = warp_n * 64 + ns * 8 + (lane & 3) * 2;
        float2 bv = __ldg((const float2*)(bias1 + c));
        float o0 = fmaxf(acc[ns][0] + bv.x, 0.f);
        float o1 = fmaxf(acc[ns][1] + bv.y, 0.f);
        float o2 = fmaxf(acc[ns][2] + bv.x, 0.f);
        float o3 = fmaxf(acc[ns][3] + bv.y, 0.f);
        int frag = warp_m * 8 + warp_n * 4 + (ns >> 1);
        int base = frag * FRAG_STRIDE + lane * 16 + (ns & 1) * 8;
        uint32_t h01b0 = bfbits(o0), h01b1 = bfbits(o1);
        uint32_t h23b0 = bfbits(o2), h23b1 = bfbits(o3);
        *(uint32_t*)(smem + base)     = h01b0 | (h01b1 << 16);
        *(uint32_t*)(smem + base + 4) = h23b0 | (h23b1 << 16);
        *(uint32_t*)(smem + A_MAT_BYTES + base) =
            pack_bf2(o0 - bf2f((unsigned short)h01b0), o1 - bf2f((unsigned short)h01b1));
        *(uint32_t*)(smem + A_MAT_BYTES + base + 4) =
            pack_bf2(o2 - bf2f((unsigned short)h23b0), o3 - bf2f((unsigned short)h23b1));
    }
    __syncthreads();

    // =========== MMA stage 2: h1 @ W2 ===========
#pragma unroll
    for (int j = 0; j < 8; j++)
#pragma unroll
        for (int q = 0; q < 4; q++) acc[j][q] = 0.f;
    {
        const uint2* wh = (const uint2*)&g_wimg[mat + 1][0][0];
        const uint2* wl = (const uint2*)&g_wimg[mat + 1][1][0];
#pragma unroll
        for (int k8 = 0; k8 < 8; k8++) {
            int fb = (warp_m * 8 + k8) * FRAG_STRIDE + lane * 16;
            uint4 ah = *(const uint4*)(smem + fb);
            uint4 al = *(const uint4*)(smem + A_MAT_BYTES + fb);
            uint2 bh[8], bl[8];
#pragma unroll
            for (int ns = 0; ns < 8; ns++) {
                int bi = (k8 * 16 + warp_n * 8 + ns) * 32 + lane;
                bh[ns] = __ldg(&wh[bi]);
                bl[ns] = __ldg(&wl[bi]);
            }
#pragma unroll
            for (int ns = 0; ns < 8; ns++) {
                MMA_BF16(acc[ns], ah, bh[ns]);
                MMA_BF16(acc[ns], ah, bl[ns]);
                MMA_BF16(acc[ns], al, bh[ns]);
            }
        }
    }

    // =========== epilogue: bias2 + act2 + store + fused BN stats ===========
    float* Out = (FMODE == 0) ? g_h2 : outP;
    int r0 = mbase + warp_m * 16 + (lane >> 2);
#pragma unroll
    for (int ns = 0; ns < 8; ns++) {
        int c = warp_n * 64 + ns * 8 + (lane & 3) * 2;
        float2 bv = __ldg((const float2*)(bias2 + c));
        float o0 = acc[ns][0] + bv.x;
        float o1 = acc[ns][1] + bv.y;
        float o2 = acc[ns][2] + bv.x;
        float o3 = acc[ns][3] + bv.y;
        if (FMODE == 0) {
            o0 = fmaxf(o0, 0.f); o1 = fmaxf(o1, 0.f);
            o2 = fmaxf(o2, 0.f); o3 = fmaxf(o3, 0.f);
        } else {
            o0 = tanhf(o0); o1 = tanhf(o1); o2 = tanhf(o2); o3 = tanhf(o3);
        }
        bool v0 = (r0 < N_NODES), v1 = (r0 + 8 < N_NODES);
        if (v0) *(float2*)(Out + (size_t)r0 * DD + c) = make_float2(o0, o1);
        if (v1) *(float2*)(Out + (size_t)(r0 + 8) * DD + c) = make_float2(o2, o3);
        float s0 = 0.f, s1 = 0.f, q0 = 0.f, q1 = 0.f;
        if (v0) { s0 += o0; s1 += o1; q0 += o0 * o0; q1 += o1 * o1; }
        if (v1) { s0 += o2; s1 += o3; q0 += o2 * o2; q1 += o3 * o3; }
#pragma unroll
        for (int off = 4; off <= 16; off <<= 1) {
            s0 += __shfl_xor_sync(0xffffffffu, s0, off);
            s1 += __shfl_xor_sync(0xffffffffu, s1, off);
            q0 += __shfl_xor_sync(0xffffffffu, q0, off);
            q1 += __shfl_xor_sync(0xffffffffu, q1, off);
        }
        if (lane < 4) {
            atomicAdd(&sstat[c],           s0);
            atomicAdd(&sstat[c + 1],       s1);
            atomicAdd(&sstat[128 + c],     q0);
            atomicAdd(&sstat[128 + c + 1], q1);
        }
    }
    __syncthreads();
    atomicAdd(&statsOut[tid], sstat[tid]);
}

// ================= fused batchnorm for 4 output layers (in-place on d_out) =================
__global__ void __launch_bounds__(256) bn4_kernel(
    float* __restrict__ outp,
    const float* __restrict__ gamma, const float* __restrict__ beta)
{
    __shared__ float sm_scale[4 * DD], sm_shift[4 * DD];
    int tid = threadIdx.x;
    for (int i = tid; i < 4 * DD; i += 256) {
        int L = i >> 7, c = i & 127;
        const float* st = g_statsL[3 + L];
        float mean = st[c] * (1.0f / N_NODES);
        float var  = st[DD + c] * (1.0f / N_NODES) - mean * mean;
        float rstd = rsqrtf(var + BN_EPS);
        float g = gamma[(3 + L) * DD + c], b = beta[(3 + L) * DD + c];
        sm_scale[i] = rstd * g;
        sm_shift[i] = b - mean * rstd * g;
    }
    __syncthreads();
    const int per_layer4 = N_NODES * DD / 4;
    int idx = blockIdx.x * 256 + tid;
    if (idx < 4 * per_layer4) {
        int L = idx / per_layer4;
        int w = idx - L * per_layer4;
        int c = L * DD + ((w * 4) & (DD - 1));
        float4 v = ((const float4*)outp)[idx];
        float4 r;
        r.x = v.x * sm_scale[c]     + sm_shift[c];
        r.y = v.y * sm_scale[c + 1] + sm_shift[c + 1];
        r.z = v.z * sm_scale[c + 2] + sm_shift[c + 2];
        r.w = v.w * sm_scale[c + 3] + sm_shift[c + 3];
        ((float4*)outp)[idx] = r;
    }
}

// ================= launcher =================
extern "C" void kernel_launch(void* const* d_in, const int* in_sizes, int n_in,
                              void* d_out, int out_size)
{
    const float* x     = (const float*)d_in[0];
    const int*   ei    = (const int*)d_in[1];     // int32 (JAX x64 disabled)
    const float* W1    = (const float*)d_in[3];
    const float* b1    = (const float*)d_in[4];
    const float* W2    = (const float*)d_in[5];
    const float* b2    = (const float*)d_in[6];
    const float* gamma = (const float*)d_in[7];
    const float* beta  = (const float*)d_in[8];
    float*       out   = (float*)d_out;

    const int* src = ei;
    const int* dst = ei + N_EDGES;

    cudaFuncSetAttribute(fused_mma<0>, cudaFuncAttributeMaxDynamicSharedMemorySize, SMEM_BYTES);
    cudaFuncSetAttribute(fused_mma<1>, cudaFuncAttributeMaxDynamicSharedMemorySize, SMEM_BYTES);
    cudaFuncSetAttribute(fused_mma<2>, cudaFuncAttributeMaxDynamicSharedMemorySize, SMEM_BYTES);

    float* statsBase = nullptr;
    cudaGetSymbolAddress((void**)&statsBase, g_statsL);
    float* h2p = nullptr;
    cudaGetSymbolAddress((void**)&h2p, g_h2);

    const int EG = (N_EDGES + 255) / 256;
    const int NG = (N_NODES + 255) / 256;
    const int AG = (N_NODES * 32 + 255) / 256;
    const int GG = NT64;
    const int WG = (14 * DD * DD + 255) / 256;
    const int B4 = (4 * N_NODES * DD / 4 + 255) / 256;

    // one-time per-call prep
    zero_cnt_kernel<<<NG, 256>>>();
    hist_kernel<<<EG, 256>>>(dst);
    wconv_kernel<<<WG, 256>>>(W1, W2);
    scan1_kernel<<<NG, 256>>>();
    scan2_kernel<<<1, 256>>>(NG);
    scan3_kernel<<<NG, 256>>>();
    fill_kernel<<<EG, 256>>>(src, dst);

    // ---- GC layers 0-2: agg + fused dual-GEMM (prev BN folded into staging) ----
    for (int l = 0; l < 3; l++) {
        const float* xin = (l == 0) ? x : h2p;
        const float* bnst = (l == 0) ? nullptr : statsBase + (l - 1) * 2 * DD;
        agg_kernel<<<AG, 256>>>(xin);
        fused_mma<0><<<GG, 256, SMEM_BYTES>>>(
            xin, l * 2, b1 + (size_t)l * DD, b2 + (size_t)l * DD,
            statsBase + l * 2 * DD, bnst,
            gamma + (size_t)(l - 1) * DD, beta + (size_t)(l - 1) * DD, nullptr);
    }

    // ---- output layers 3-6: shared input/agg; fused dual-GEMM -> d_out ----
    agg_kernel<<<AG, 256>>>(h2p);
    for (int l = 3; l < 7; l++) {
        float* op = out + (size_t)(l - 3) * N_NODES * DD;
        if (l == 3)
            fused_mma<1><<<GG, 256, SMEM_BYTES>>>(
                h2p, l * 2, b1 + (size_t)l * DD, b2 + (size_t)l * DD,
                statsBase + l * 2 * DD, statsBase + 2 * 2 * DD,
                gamma + (size_t)2 * DD, beta + (size_t)2 * DD, op);
        else
            fused_mma<2><<<GG, 256, SMEM_BYTES>>>(
                nullptr, l * 2, b1 + (size_t)l * DD, b2 + (size_t)l * DD,
                statsBase + l * 2 * DD, nullptr, nullptr, nullptr, op);
    }
    bn4_kernel<<<B4, 256>>>(out, gamma, beta);
}